// round 3
// baseline (speedup 1.0000x reference)
#include <cuda_runtime.h>
#include <math.h>

#define BATCH 64
#define NTOK  4096
#define IND   256
#define SD    256
#define NS    8
#define ROWS_IN (BATCH*NTOK)   /* 262144 */
#define SROWS   (BATCH*NS)     /* 512 */

// ---------------- device scratch (allocation-free rule: globals) -------------
__device__ float g_kv[134217728];        // [ROWS_IN][512]  k | v interleaved per row
__device__ float g_mean[ROWS_IN];
__device__ float g_rstd[ROWS_IN];
__device__ float g_Wkv[256*512];         // g-folded [Wk|Wv]
__device__ float g_colW[512];
__device__ float g_biasW[512];
__device__ float g_wihT[256*768];
__device__ float g_whhT[256*768];
__device__ float g_slotsA[SROWS*256];
__device__ float g_slotsB[SROWS*256];
__device__ float g_sn[SROWS*256];
__device__ float g_q[SROWS*256];
__device__ float g_attn[2097152];        // [B][N][8]
__device__ float g_colsum[SROWS];        // [B][S]
__device__ float g_upd[SROWS*256];
__device__ float g_gi[SROWS*768];
__device__ float g_gh[SROWS*768];
__device__ float g_hbuf[SROWS*1024];

// ---------------- weight prep ------------------------------------------------
__global__ void prep_weights(const float* __restrict__ Wk, const float* __restrict__ Wv,
                             const float* __restrict__ g,
                             const float* __restrict__ wih, const float* __restrict__ whh) {
    int idx = blockIdx.x * blockDim.x + threadIdx.x;
    if (idx < 256*512) {
        int c = idx >> 9, d2 = idx & 511;
        float w = (d2 < 256) ? Wk[c*256 + d2] : Wv[c*256 + (d2 - 256)];
        g_Wkv[idx] = g[c] * w;
    }
    if (idx < 256*768) {
        int d = idx / 768, j = idx - d*768;
        g_wihT[idx] = wih[j*256 + d];
        g_whhT[idx] = whh[j*256 + d];
    }
}

__global__ void colsum_bias(const float* __restrict__ Wk, const float* __restrict__ Wv,
                            const float* __restrict__ bvec) {
    int d2 = blockIdx.x * 256 + threadIdx.x;   // 0..511
    float cs = 0.f, bs = 0.f;
    for (int c = 0; c < 256; c++) {
        cs += g_Wkv[c*512 + d2];
        float w = (d2 < 256) ? Wk[c*256 + d2] : Wv[c*256 + (d2 - 256)];
        bs += bvec[c] * w;
    }
    g_colW[d2] = cs;
    g_biasW[d2] = bs;
}

// ---------------- slots init -------------------------------------------------
__global__ void slots_init(const float* __restrict__ noise, const float* __restrict__ mu,
                           const float* __restrict__ lsig) {
    int idx = blockIdx.x * 256 + threadIdx.x;  // < 131072
    int d = idx & 255;
    g_slotsA[idx] = mu[d] + expf(lsig[d]) * noise[idx];
}

// ---------------- per-row LN stats for inputs (warp per row) -----------------
__global__ void row_stats(const float* __restrict__ x) {
    int row  = blockIdx.x * 8 + (threadIdx.x >> 5);
    int lane = threadIdx.x & 31;
    const float4* p = (const float4*)(x + (size_t)row * 256);
    float4 a = p[lane], b = p[lane + 32];
    float s = a.x + a.y + a.z + a.w + b.x + b.y + b.z + b.w;
    float q = a.x*a.x + a.y*a.y + a.z*a.z + a.w*a.w
            + b.x*b.x + b.y*b.y + b.z*b.z + b.w*b.w;
    #pragma unroll
    for (int off = 16; off; off >>= 1) {
        s += __shfl_xor_sync(0xffffffffu, s, off);
        q += __shfl_xor_sync(0xffffffffu, q, off);
    }
    if (lane == 0) {
        float m = s * (1.f/256.f);
        float var = q * (1.f/256.f) - m*m;
        g_mean[row] = m;
        g_rstd[row] = rsqrtf(var + 1e-5f);
    }
}

// ---------------- small LN (block per row, D=256) ----------------------------
__global__ void ln_rows(const float* __restrict__ in, float* __restrict__ out,
                        const float* __restrict__ g, const float* __restrict__ b) {
    int row = blockIdx.x, t = threadIdx.x;
    float x = in[row*256 + t];
    float s = x, q = x*x;
    #pragma unroll
    for (int off = 16; off; off >>= 1) {
        s += __shfl_xor_sync(0xffffffffu, s, off);
        q += __shfl_xor_sync(0xffffffffu, q, off);
    }
    __shared__ float red[16];
    int w = t >> 5, l = t & 31;
    if (l == 0) { red[w] = s; red[8 + w] = q; }
    __syncthreads();
    float S = 0.f, Q = 0.f;
    #pragma unroll
    for (int i = 0; i < 8; i++) { S += red[i]; Q += red[8 + i]; }
    float m = S * (1.f/256.f);
    float var = Q * (1.f/256.f) - m*m;
    float r = rsqrtf(var + 1e-5f);
    out[row*256 + t] = (x - m) * r * g[t] + b[t];
}

// ---------------- generic tiled SGEMM ----------------------------------------
// MODE: 0 plain | 1 +bias | 2 relu(+bias) | 3 +bias+residual(C) | 4 LN-fold epilogue
template<int BM, int BN, int BK, int TM, int TN, int MODE>
__global__ __launch_bounds__(256)
void sgemm_kernel(const float* __restrict__ A, const float* __restrict__ B,
                  float* __restrict__ C, int M, int N, int K,
                  const float* __restrict__ bias,
                  const float* __restrict__ mean,
                  const float* __restrict__ rstd,
                  const float* __restrict__ colW) {
    static_assert((BM/TM)*(BN/TN) == 256, "256 threads");
    static_assert((BM*BK) == 4*256 && (BN*BK) == 4*256, "one float4 per thread per tile");
    __shared__ float As[BK][BM];
    __shared__ float Bs[BK][BN];
    int tid = threadIdx.x;
    int tx = tid % (BN/TN);
    int ty = tid / (BN/TN);
    int rowBase = blockIdx.y * BM;
    int colBase = blockIdx.x * BN;

    int a_r = tid / (BK/4);
    int a_c = (tid % (BK/4)) * 4;
    int b_r = tid / (BN/4);
    int b_c = (tid % (BN/4)) * 4;

    float acc[TM][TN];
    #pragma unroll
    for (int i = 0; i < TM; i++)
        #pragma unroll
        for (int j = 0; j < TN; j++) acc[i][j] = 0.f;

    for (int k0 = 0; k0 < K; k0 += BK) {
        float4 av = *(const float4*)&A[(size_t)(rowBase + a_r) * K + k0 + a_c];
        As[a_c + 0][a_r] = av.x;
        As[a_c + 1][a_r] = av.y;
        As[a_c + 2][a_r] = av.z;
        As[a_c + 3][a_r] = av.w;
        float4 bv = *(const float4*)&B[(size_t)(k0 + b_r) * N + colBase + b_c];
        *(float4*)&Bs[b_r][b_c] = bv;
        __syncthreads();
        #pragma unroll
        for (int kk = 0; kk < BK; kk++) {
            float af[TM], bf[TN];
            #pragma unroll
            for (int i = 0; i < TM; i++) af[i] = As[kk][ty*TM + i];
            #pragma unroll
            for (int j = 0; j < TN; j++) bf[j] = Bs[kk][tx*TN + j];
            #pragma unroll
            for (int i = 0; i < TM; i++)
                #pragma unroll
                for (int j = 0; j < TN; j++)
                    acc[i][j] += af[i] * bf[j];
        }
        __syncthreads();
    }

    #pragma unroll
    for (int i = 0; i < TM; i++) {
        int row = rowBase + ty*TM + i;
        #pragma unroll
        for (int j = 0; j < TN; j++) {
            int col = colBase + tx*TN + j;
            float v = acc[i][j];
            if constexpr (MODE == 1 || MODE == 2 || MODE == 3) v += bias[col];
            if constexpr (MODE == 2) v = fmaxf(v, 0.f);
            if constexpr (MODE == 3) v += C[(size_t)row * N + col];
            if constexpr (MODE == 4)
                v = rstd[row] * (v - mean[row] * colW[col]) + bias[col];
            C[(size_t)row * N + col] = v;
        }
    }
}

// ---------------- zero colsum + updates --------------------------------------
__global__ void zero_iter() {
    int idx = blockIdx.x * 256 + threadIdx.x;   // 512*256 = 131072
    if (idx < SROWS*256) g_upd[idx] = 0.f;
    if (idx < SROWS)     g_colsum[idx] = 0.f;
}

// ---------------- logits + softmax + column-sum (warp per token) -------------
__global__ __launch_bounds__(256) void logits_softmax() {
    int b = blockIdx.y;
    __shared__ float qs[8*256];
    __shared__ float cs[8];
    int t = threadIdx.x;
    #pragma unroll
    for (int i = 0; i < 8; i++) qs[i*256 + t] = g_q[b*2048 + i*256 + t];
    if (t < 8) cs[t] = 0.f;
    __syncthreads();

    int warp = t >> 5, lane = t & 31;
    float lsum = 0.f;
    for (int it = 0; it < 64; it++) {
        int n = blockIdx.x * 512 + warp * 64 + it;
        const float* krow = g_kv + (size_t)(b * NTOK + n) * 512;
        float4 k0 = *(const float4*)&krow[lane*4];
        float4 k1 = *(const float4*)&krow[128 + lane*4];
        float acc[8];
        #pragma unroll
        for (int s = 0; s < 8; s++) {
            const float* qr = &qs[s*256];
            float4 q0 = *(const float4*)&qr[lane*4];
            float4 q1 = *(const float4*)&qr[128 + lane*4];
            acc[s] = k0.x*q0.x + k0.y*q0.y + k0.z*q0.z + k0.w*q0.w
                   + k1.x*q1.x + k1.y*q1.y + k1.z*q1.z + k1.w*q1.w;
        }
        #pragma unroll
        for (int s = 0; s < 8; s++)
            #pragma unroll
            for (int off = 16; off; off >>= 1)
                acc[s] += __shfl_xor_sync(0xffffffffu, acc[s], off);
        // softmax over 8 slots (scale 1/16)
        float mx = -1e30f;
        #pragma unroll
        for (int s = 0; s < 8; s++) { acc[s] *= 0.0625f; mx = fmaxf(mx, acc[s]); }
        float e[8], se = 0.f;
        #pragma unroll
        for (int s = 0; s < 8; s++) { e[s] = expf(acc[s] - mx); se += e[s]; }
        float inv = 1.f / se;
        if (lane < 8) {
            float a = e[lane] * inv;
            g_attn[(size_t)(b * NTOK + n) * 8 + lane] = a;
            lsum += a;
        }
    }
    if (lane < 8) atomicAdd(&cs[lane], lsum);
    __syncthreads();
    if (t < 8) atomicAdd(&g_colsum[b*8 + t], cs[t]);
}

// ---------------- updates = (attn/colsum)^T @ v ------------------------------
__global__ __launch_bounds__(256) void updates_kernel() {
    int b = blockIdx.y;
    int t = threadIdx.x;                 // d = t
    __shared__ float aw[32*8];
    __shared__ float inv[8];
    if (t < 8) inv[t] = 1.f / (g_colsum[b*8 + t] + 1e-8f);
    float acc[8];
    #pragma unroll
    for (int s = 0; s < 8; s++) acc[s] = 0.f;

    for (int stage = 0; stage < 16; stage++) {
        int base = blockIdx.x * 512 + stage * 32;
        aw[t] = g_attn[(size_t)(b * NTOK + base) * 8 + t];
        __syncthreads();
        #pragma unroll 4
        for (int tok = 0; tok < 32; tok++) {
            float vd = g_kv[(size_t)(b * NTOK + base + tok) * 512 + 256 + t];
            float4 w0 = *(const float4*)&aw[tok*8];
            float4 w1 = *(const float4*)&aw[tok*8 + 4];
            acc[0] += w0.x * vd; acc[1] += w0.y * vd;
            acc[2] += w0.z * vd; acc[3] += w0.w * vd;
            acc[4] += w1.x * vd; acc[5] += w1.y * vd;
            acc[6] += w1.z * vd; acc[7] += w1.w * vd;
        }
        __syncthreads();
    }
    #pragma unroll
    for (int s = 0; s < 8; s++)
        atomicAdd(&g_upd[(b*8 + s)*256 + t], acc[s] * inv[s]);
}

// ---------------- GRU gating -------------------------------------------------
__global__ void gate_kernel(const float* __restrict__ prev, float* __restrict__ outp) {
    int idx = blockIdx.x * 256 + threadIdx.x;     // 131072
    int row = idx >> 8, d = idx & 255;
    const float* gi = g_gi + row*768;
    const float* gh = g_gh + row*768;
    float r = 1.f / (1.f + expf(-(gi[d]       + gh[d])));
    float z = 1.f / (1.f + expf(-(gi[256 + d] + gh[256 + d])));
    float n = tanhf(gi[512 + d] + r * gh[512 + d]);
    outp[idx] = (1.f - z) * n + z * prev[idx];
}

// ---------------- attn transpose [B,N,8] -> [B,8,N] --------------------------
__global__ void transpose_attn(float* __restrict__ out) {
    int b = blockIdx.y;
    int base = blockIdx.x * 256;
    int t = threadIdx.x;
    __shared__ float sm[256*9];
    #pragma unroll
    for (int i = 0; i < 8; i++) {
        int lin = i*256 + t;
        float v = g_attn[(size_t)(b * NTOK + base) * 8 + lin];
        sm[(lin >> 3) * 9 + (lin & 7)] = v;
    }
    __syncthreads();
    #pragma unroll
    for (int s = 0; s < 8; s++)
        out[(size_t)b * 8 * NTOK + s * NTOK + base + t] = sm[t*9 + s];
}

// ---------------- copy slots to output ---------------------------------------
__global__ void copy_slots(const float* __restrict__ src, float* __restrict__ dst) {
    int idx = blockIdx.x * 256 + threadIdx.x;
    dst[idx] = src[idx];
}

// =============================================================================
extern "C" void kernel_launch(void* const* d_in, const int* in_sizes, int n_in,
                              void* d_out, int out_size) {
    const float* inputs   = (const float*)d_in[0];
    const float* noise    = (const float*)d_in[1];
    const float* mu       = (const float*)d_in[2];
    const float* lsig     = (const float*)d_in[3];
    const float* ln_in_g  = (const float*)d_in[4];
    const float* ln_in_b  = (const float*)d_in[5];
    const float* ln_s_g   = (const float*)d_in[6];
    const float* ln_s_b   = (const float*)d_in[7];
    const float* ln_m_g   = (const float*)d_in[8];
    const float* ln_m_b   = (const float*)d_in[9];
    const float* Wq       = (const float*)d_in[10];
    const float* Wk       = (const float*)d_in[11];
    const float* Wv       = (const float*)d_in[12];
    const float* wih      = (const float*)d_in[13];
    const float* whh      = (const float*)d_in[14];
    const float* b_ih     = (const float*)d_in[15];
    const float* b_hh     = (const float*)d_in[16];
    const float* mlp_w1   = (const float*)d_in[17];
    const float* mlp_b1   = (const float*)d_in[18];
    const float* mlp_w2   = (const float*)d_in[19];
    const float* mlp_b2   = (const float*)d_in[20];
    float* out = (float*)d_out;

    float *p_kv, *p_mean, *p_rstd, *p_Wkv, *p_colW, *p_biasW;
    float *p_wihT, *p_whhT, *p_sA, *p_sB, *p_sn, *p_q, *p_upd, *p_gi, *p_gh, *p_h;
    cudaGetSymbolAddress((void**)&p_kv,   g_kv);
    cudaGetSymbolAddress((void**)&p_mean, g_mean);
    cudaGetSymbolAddress((void**)&p_rstd, g_rstd);
    cudaGetSymbolAddress((void**)&p_Wkv,  g_Wkv);
    cudaGetSymbolAddress((void**)&p_colW, g_colW);
    cudaGetSymbolAddress((void**)&p_biasW,g_biasW);
    cudaGetSymbolAddress((void**)&p_wihT, g_wihT);
    cudaGetSymbolAddress((void**)&p_whhT, g_whhT);
    cudaGetSymbolAddress((void**)&p_sA,   g_slotsA);
    cudaGetSymbolAddress((void**)&p_sB,   g_slotsB);
    cudaGetSymbolAddress((void**)&p_sn,   g_sn);
    cudaGetSymbolAddress((void**)&p_q,    g_q);
    cudaGetSymbolAddress((void**)&p_upd,  g_upd);
    cudaGetSymbolAddress((void**)&p_gi,   g_gi);
    cudaGetSymbolAddress((void**)&p_gh,   g_gh);
    cudaGetSymbolAddress((void**)&p_h,    g_hbuf);

    // ---- prep ----
    prep_weights<<<768, 256>>>(Wk, Wv, ln_in_g, wih, whh);
    colsum_bias<<<2, 256>>>(Wk, Wv, ln_in_b);
    slots_init<<<512, 256>>>(noise, mu, lsig);
    row_stats<<<ROWS_IN/8, 256>>>(inputs);

    // ---- k|v = LN(x) @ [Wk|Wv]  (LN folded into epilogue) ----
    sgemm_kernel<128,128,8,8,8,4><<<dim3(512/128, ROWS_IN/128), 256>>>(
        inputs, p_Wkv, p_kv, ROWS_IN, 512, 256, p_biasW, p_mean, p_rstd, p_colW);

    float* prev = p_sA;
    float* next = p_sB;
    for (int it = 0; it < 3; it++) {
        ln_rows<<<SROWS, 256>>>(prev, p_sn, ln_s_g, ln_s_b);
        sgemm_kernel<64,64,16,4,4,0><<<dim3(256/64, SROWS/64), 256>>>(
            p_sn, Wq, p_q, SROWS, 256, 256, nullptr, nullptr, nullptr, nullptr);
        zero_iter<<<512, 256>>>();
        logits_softmax<<<dim3(NTOK/512, BATCH), 256>>>();
        updates_kernel<<<dim3(NTOK/512, BATCH), 256>>>();
        sgemm_kernel<64,64,16,4,4,1><<<dim3(768/64, SROWS/64), 256>>>(
            p_upd, p_wihT, p_gi, SROWS, 768, 256, b_ih, nullptr, nullptr, nullptr);
        sgemm_kernel<64,64,16,4,4,1><<<dim3(768/64, SROWS/64), 256>>>(
            prev, p_whhT, p_gh, SROWS, 768, 256, b_hh, nullptr, nullptr, nullptr);
        gate_kernel<<<512, 256>>>(prev, next);
        ln_rows<<<SROWS, 256>>>(next, p_sn, ln_m_g, ln_m_b);
        sgemm_kernel<64,64,16,4,4,2><<<dim3(1024/64, SROWS/64), 256>>>(
            p_sn, mlp_w1, p_h, SROWS, 1024, 256, mlp_b1, nullptr, nullptr, nullptr);
        sgemm_kernel<64,64,16,4,4,3><<<dim3(256/64, SROWS/64), 256>>>(
            p_h, mlp_w2, next, SROWS, 256, 1024, mlp_b2, nullptr, nullptr, nullptr);
        float* tmp = prev; prev = next; next = tmp;
    }

    // ---- outputs: slots [B,S,D] then attn^T [B,S,N] ----
    copy_slots<<<SROWS*256/256, 256>>>(prev, out);
    transpose_attn<<<dim3(NTOK/256, BATCH), 256>>>(out + SROWS*256);
}

// round 4
// speedup vs baseline: 2.0049x; 2.0049x over previous
#include <cuda_runtime.h>
#include <math.h>

#define BATCH 64
#define NTOK  4096
#define ROWS_IN (BATCH*NTOK)   /* 262144 */
#define SROWS   (BATCH*8)      /* 512 */

// ---------------- device scratch ---------------------------------------------
__device__ float g_xn[67108864];         // [ROWS_IN][256] normalized inputs (no g,b)
__device__ float g_attn[2097152];        // [B][N][8]
__device__ float g_Uacc[SROWS*256];      // un-normalized attn^T @ xn
__device__ float g_colsum[SROWS];
__device__ float g_inv[SROWS];
__device__ float g_cb[SROWS];
__device__ float g_WkgT[65536];          // [d][c] = g[c]*Wk[c][d]
__device__ float g_Wvg[65536];           // [c][d] = g[c]*Wv[c][d]
__device__ float g_WqWk[65536];          // Wq @ WkgT
__device__ float g_bk[256];              // b_ln @ Wk
__device__ float g_bv[256];              // b_ln @ Wv
__device__ float g_wqbk[256];            // Wq @ bk
__device__ float g_wihT[256*768];
__device__ float g_whhT[256*768];
__device__ float g_slotsA[SROWS*256];
__device__ float g_slotsB[SROWS*256];
__device__ float g_sn[SROWS*256];
__device__ float g_Qp[SROWS*256];
__device__ float g_qb[SROWS];
__device__ float g_upd[SROWS*256];
__device__ float g_gi[SROWS*768];
__device__ float g_gh[SROWS*768];
__device__ float g_hbuf[SROWS*1024];

// ---------------- weight prep ------------------------------------------------
__global__ void prep_weights(const float* __restrict__ Wk, const float* __restrict__ Wv,
                             const float* __restrict__ g,
                             const float* __restrict__ wih, const float* __restrict__ whh) {
    int idx = blockIdx.x * 256 + threadIdx.x;   // up to 196608
    if (idx < 65536) {
        int d = idx >> 8, c = idx & 255;
        g_WkgT[idx] = g[c] * Wk[c*256 + d];
        int c2 = idx >> 8;                       // elementwise for Wvg
        g_Wvg[idx] = g[c2] * Wv[idx];
    }
    if (idx < 196608) {
        int d = idx / 768, j = idx - d*768;
        g_wihT[idx] = wih[j*256 + d];
        g_whhT[idx] = whh[j*256 + d];
    }
}

__global__ void bias_vec(const float* __restrict__ Wk, const float* __restrict__ Wv,
                         const float* __restrict__ b) {
    int t = threadIdx.x;   // 512
    if (t < 256) {
        float s = 0.f;
        for (int c = 0; c < 256; c++) s += b[c] * Wk[c*256 + t];
        g_bk[t] = s;
    } else {
        int d = t - 256;
        float s = 0.f;
        for (int c = 0; c < 256; c++) s += b[c] * Wv[c*256 + d];
        g_bv[d] = s;
    }
}

__global__ void wqbk_kernel(const float* __restrict__ Wq) {
    int e = threadIdx.x;
    float s = 0.f;
    for (int d = 0; d < 256; d++) s += Wq[e*256 + d] * g_bk[d];
    g_wqbk[e] = s;
}

// ---------------- slots init -------------------------------------------------
__global__ void slots_init(const float* __restrict__ noise, const float* __restrict__ mu,
                           const float* __restrict__ lsig) {
    int idx = blockIdx.x * 256 + threadIdx.x;  // 131072
    int d = idx & 255;
    g_slotsA[idx] = mu[d] + expf(lsig[d]) * noise[idx];
}

// ---------------- LN of inputs (no gamma/beta), write xn ---------------------
__global__ void ln_write(const float* __restrict__ x) {
    int row  = blockIdx.x * 8 + (threadIdx.x >> 5);
    int lane = threadIdx.x & 31;
    const float4* p = (const float4*)(x + (size_t)row * 256);
    float4 a = p[lane], c = p[lane + 32];
    float s = a.x + a.y + a.z + a.w + c.x + c.y + c.z + c.w;
    float q = a.x*a.x + a.y*a.y + a.z*a.z + a.w*a.w
            + c.x*c.x + c.y*c.y + c.z*c.z + c.w*c.w;
    #pragma unroll
    for (int off = 16; off; off >>= 1) {
        s += __shfl_xor_sync(0xffffffffu, s, off);
        q += __shfl_xor_sync(0xffffffffu, q, off);
    }
    float m = s * (1.f/256.f);
    float var = q * (1.f/256.f) - m*m;
    float r = rsqrtf(var + 1e-5f);
    float4* o = (float4*)(g_xn + (size_t)row * 256);
    a.x = (a.x-m)*r; a.y = (a.y-m)*r; a.z = (a.z-m)*r; a.w = (a.w-m)*r;
    c.x = (c.x-m)*r; c.y = (c.y-m)*r; c.z = (c.z-m)*r; c.w = (c.w-m)*r;
    o[lane] = a; o[lane + 32] = c;
}

// ---------------- small LN (block per row, D=256) ----------------------------
__global__ void ln_rows(const float* __restrict__ in, float* __restrict__ out,
                        const float* __restrict__ g, const float* __restrict__ b) {
    int row = blockIdx.x, t = threadIdx.x;
    float x = in[row*256 + t];
    float s = x, q = x*x;
    #pragma unroll
    for (int off = 16; off; off >>= 1) {
        s += __shfl_xor_sync(0xffffffffu, s, off);
        q += __shfl_xor_sync(0xffffffffu, q, off);
    }
    __shared__ float red[16];
    int w = t >> 5, l = t & 31;
    if (l == 0) { red[w] = s; red[8 + w] = q; }
    __syncthreads();
    float S = 0.f, Q = 0.f;
    #pragma unroll
    for (int i = 0; i < 8; i++) { S += red[i]; Q += red[8 + i]; }
    float m = S * (1.f/256.f);
    float var = Q * (1.f/256.f) - m*m;
    float r = rsqrtf(var + 1e-5f);
    out[row*256 + t] = (x - m) * r * g[t] + b[t];
}

// ---------------- generic tiled SGEMM ----------------------------------------
// MODE: 0 plain | 1 +bias | 2 relu(+bias) | 3 +bias+residual(C) | 5 scaled+cb*bias
template<int BM, int BN, int BK, int TM, int TN, int MODE>
__global__ __launch_bounds__(256)
void sgemm_kernel(const float* __restrict__ A, const float* __restrict__ B,
                  float* __restrict__ C, int M, int N, int K,
                  const float* __restrict__ bias,
                  const float* __restrict__ rs1,   // MODE5: inv per row
                  const float* __restrict__ rs2) { // MODE5: cb  per row
    static_assert((BM/TM)*(BN/TN) == 256, "256 threads");
    static_assert((BM*BK) == 4*256 && (BN*BK) == 4*256, "one float4 per thread per tile");
    __shared__ float As[BK][BM];
    __shared__ float Bs[BK][BN];
    int tid = threadIdx.x;
    int tx = tid % (BN/TN);
    int ty = tid / (BN/TN);
    int rowBase = blockIdx.y * BM;
    int colBase = blockIdx.x * BN;

    int a_r = tid / (BK/4);
    int a_c = (tid % (BK/4)) * 4;
    int b_r = tid / (BN/4);
    int b_c = (tid % (BN/4)) * 4;

    float acc[TM][TN];
    #pragma unroll
    for (int i = 0; i < TM; i++)
        #pragma unroll
        for (int j = 0; j < TN; j++) acc[i][j] = 0.f;

    for (int k0 = 0; k0 < K; k0 += BK) {
        float4 av = *(const float4*)&A[(size_t)(rowBase + a_r) * K + k0 + a_c];
        As[a_c + 0][a_r] = av.x;
        As[a_c + 1][a_r] = av.y;
        As[a_c + 2][a_r] = av.z;
        As[a_c + 3][a_r] = av.w;
        float4 bv = *(const float4*)&B[(size_t)(k0 + b_r) * N + colBase + b_c];
        *(float4*)&Bs[b_r][b_c] = bv;
        __syncthreads();
        #pragma unroll
        for (int kk = 0; kk < BK; kk++) {
            float af[TM], bf[TN];
            #pragma unroll
            for (int i = 0; i < TM; i++) af[i] = As[kk][ty*TM + i];
            #pragma unroll
            for (int j = 0; j < TN; j++) bf[j] = Bs[kk][tx*TN + j];
            #pragma unroll
            for (int i = 0; i < TM; i++)
                #pragma unroll
                for (int j = 0; j < TN; j++)
                    acc[i][j] += af[i] * bf[j];
        }
        __syncthreads();
    }

    #pragma unroll
    for (int i = 0; i < TM; i++) {
        int row = rowBase + ty*TM + i;
        #pragma unroll
        for (int j = 0; j < TN; j++) {
            int col = colBase + tx*TN + j;
            float v = acc[i][j];
            if constexpr (MODE == 1 || MODE == 2 || MODE == 3) v += bias[col];
            if constexpr (MODE == 2) v = fmaxf(v, 0.f);
            if constexpr (MODE == 3) v += C[(size_t)row * N + col];
            if constexpr (MODE == 5) v = v * rs1[row] + rs2[row] * bias[col];
            C[(size_t)row * N + col] = v;
        }
    }
}

// ---------------- zero Uacc + colsum -----------------------------------------
__global__ void zero_iter() {
    int idx = blockIdx.x * 256 + threadIdx.x;   // 131072
    g_Uacc[idx] = 0.f;
    if (idx < SROWS) g_colsum[idx] = 0.f;
}

// ---------------- fused logits + softmax + attn + U accumulation -------------
__global__ __launch_bounds__(256) void fused_attn() {
    int b = blockIdx.y;
    __shared__ float qs[2048];    // Qp for 8 slots
    __shared__ float qb_s[8];
    __shared__ float cs[8];
    __shared__ float Ub[2048];
    int t = threadIdx.x;
    #pragma unroll
    for (int i = 0; i < 8; i++) {
        qs[i*256 + t] = g_Qp[b*2048 + i*256 + t];
        Ub[i*256 + t] = 0.f;
    }
    if (t < 8) { qb_s[t] = g_qb[b*8 + t]; cs[t] = 0.f; }
    __syncthreads();

    int warp = t >> 5, lane = t & 31;
    float regU[64];
    #pragma unroll
    for (int i = 0; i < 64; i++) regU[i] = 0.f;
    float lsum = 0.f;

    for (int it = 0; it < 64; it++) {
        int n = blockIdx.x * 512 + warp * 64 + it;
        const float* xr = g_xn + (size_t)(b * NTOK + n) * 256;
        float4 x0 = *(const float4*)&xr[lane*4];
        float4 x1 = *(const float4*)&xr[128 + lane*4];
        float acc[8];
        #pragma unroll
        for (int s = 0; s < 8; s++) {
            const float4 q0 = *(const float4*)&qs[s*256 + lane*4];
            const float4 q1 = *(const float4*)&qs[s*256 + 128 + lane*4];
            acc[s] = x0.x*q0.x + x0.y*q0.y + x0.z*q0.z + x0.w*q0.w
                   + x1.x*q1.x + x1.y*q1.y + x1.z*q1.z + x1.w*q1.w;
        }
        #pragma unroll
        for (int s = 0; s < 8; s++)
            #pragma unroll
            for (int off = 16; off; off >>= 1)
                acc[s] += __shfl_xor_sync(0xffffffffu, acc[s], off);
        // logits + softmax (replicated on all lanes)
        float mx = -1e30f;
        #pragma unroll
        for (int s = 0; s < 8; s++) {
            acc[s] = (acc[s] + qb_s[s]) * 0.0625f;
            mx = fmaxf(mx, acc[s]);
        }
        float a[8], se = 0.f;
        #pragma unroll
        for (int s = 0; s < 8; s++) { a[s] = expf(acc[s] - mx); se += a[s]; }
        float inv = 1.f / se;
        #pragma unroll
        for (int s = 0; s < 8; s++) a[s] *= inv;
        if (lane < 8) {
            float aval = 0.f;
            #pragma unroll
            for (int s = 0; s < 8; s++) if (lane == s) aval = a[s];
            g_attn[(size_t)(b * NTOK + n) * 8 + lane] = aval;
            lsum += aval;
        }
        #pragma unroll
        for (int s = 0; s < 8; s++) {
            regU[s*8+0] += a[s]*x0.x; regU[s*8+1] += a[s]*x0.y;
            regU[s*8+2] += a[s]*x0.z; regU[s*8+3] += a[s]*x0.w;
            regU[s*8+4] += a[s]*x1.x; regU[s*8+5] += a[s]*x1.y;
            regU[s*8+6] += a[s]*x1.z; regU[s*8+7] += a[s]*x1.w;
        }
    }
    // flush per-warp U into shared
    #pragma unroll
    for (int s = 0; s < 8; s++) {
        #pragma unroll
        for (int j = 0; j < 4; j++)
            atomicAdd(&Ub[s*256 + 4*lane + j], regU[s*8 + j]);
        #pragma unroll
        for (int j = 0; j < 4; j++)
            atomicAdd(&Ub[s*256 + 128 + 4*lane + j], regU[s*8 + 4 + j]);
    }
    if (lane < 8) atomicAdd(&cs[lane], lsum);
    __syncthreads();
    #pragma unroll
    for (int i = 0; i < 8; i++)
        atomicAdd(&g_Uacc[b*2048 + i*256 + t], Ub[i*256 + t]);
    if (t < 8) atomicAdd(&g_colsum[b*8 + t], cs[t]);
}

// ---------------- qb = sn @ wqbk ---------------------------------------------
__global__ void qb_kernel() {
    int row  = blockIdx.x * 8 + (threadIdx.x >> 5);
    int lane = threadIdx.x & 31;
    const float4* s4 = (const float4*)(g_sn + row*256);
    const float4* w4 = (const float4*)g_wqbk;
    float4 a = s4[lane], wa = w4[lane];
    float4 c = s4[lane+32], wc = w4[lane+32];
    float s = a.x*wa.x + a.y*wa.y + a.z*wa.z + a.w*wa.w
            + c.x*wc.x + c.y*wc.y + c.z*wc.z + c.w*wc.w;
    #pragma unroll
    for (int off = 16; off; off >>= 1) s += __shfl_xor_sync(0xffffffffu, s, off);
    if (lane == 0) g_qb[row] = s;
}

// ---------------- per-row scale from colsum ----------------------------------
__global__ void rowscale() {
    int row = blockIdx.x * 256 + threadIdx.x;
    if (row < SROWS) {
        float cs = g_colsum[row];
        float inv = 1.f / (cs + 1e-8f);
        g_inv[row] = inv;
        g_cb[row] = cs * inv;
    }
}

// ---------------- GRU gating -------------------------------------------------
__global__ void gate_kernel(const float* __restrict__ prev, float* __restrict__ outp) {
    int idx = blockIdx.x * 256 + threadIdx.x;     // 131072
    int row = idx >> 8, d = idx & 255;
    const float* gi = g_gi + row*768;
    const float* gh = g_gh + row*768;
    float r = 1.f / (1.f + expf(-(gi[d]       + gh[d])));
    float z = 1.f / (1.f + expf(-(gi[256 + d] + gh[256 + d])));
    float n = tanhf(gi[512 + d] + r * gh[512 + d]);
    outp[idx] = (1.f - z) * n + z * prev[idx];
}

// ---------------- attn transpose [B,N,8] -> [B,8,N] --------------------------
__global__ void transpose_attn(float* __restrict__ out) {
    int b = blockIdx.y;
    int base = blockIdx.x * 256;
    int t = threadIdx.x;
    __shared__ float sm[256*9];
    #pragma unroll
    for (int i = 0; i < 8; i++) {
        int lin = i*256 + t;
        float v = g_attn[(size_t)(b * NTOK + base) * 8 + lin];
        sm[(lin >> 3) * 9 + (lin & 7)] = v;
    }
    __syncthreads();
    #pragma unroll
    for (int s = 0; s < 8; s++)
        out[(size_t)b * 8 * NTOK + s * NTOK + base + t] = sm[t*9 + s];
}

__global__ void copy_slots(const float* __restrict__ src, float* __restrict__ dst) {
    int idx = blockIdx.x * 256 + threadIdx.x;
    dst[idx] = src[idx];
}

// =============================================================================
extern "C" void kernel_launch(void* const* d_in, const int* in_sizes, int n_in,
                              void* d_out, int out_size) {
    const float* inputs   = (const float*)d_in[0];
    const float* noise    = (const float*)d_in[1];
    const float* mu       = (const float*)d_in[2];
    const float* lsig     = (const float*)d_in[3];
    const float* ln_in_g  = (const float*)d_in[4];
    const float* ln_in_b  = (const float*)d_in[5];
    const float* ln_s_g   = (const float*)d_in[6];
    const float* ln_s_b   = (const float*)d_in[7];
    const float* ln_m_g   = (const float*)d_in[8];
    const float* ln_m_b   = (const float*)d_in[9];
    const float* Wq       = (const float*)d_in[10];
    const float* Wk       = (const float*)d_in[11];
    const float* Wv       = (const float*)d_in[12];
    const float* wih      = (const float*)d_in[13];
    const float* whh      = (const float*)d_in[14];
    const float* b_ih     = (const float*)d_in[15];
    const float* b_hh     = (const float*)d_in[16];
    const float* mlp_w1   = (const float*)d_in[17];
    const float* mlp_b1   = (const float*)d_in[18];
    const float* mlp_w2   = (const float*)d_in[19];
    const float* mlp_b2   = (const float*)d_in[20];
    float* out = (float*)d_out;

    float *p_WkgT, *p_Wvg, *p_WqWk, *p_bv;
    float *p_wihT, *p_whhT, *p_sA, *p_sB, *p_sn, *p_Qp, *p_Uacc;
    float *p_inv, *p_cb, *p_upd, *p_gi, *p_gh, *p_h;
    cudaGetSymbolAddress((void**)&p_WkgT, g_WkgT);
    cudaGetSymbolAddress((void**)&p_Wvg,  g_Wvg);
    cudaGetSymbolAddress((void**)&p_WqWk, g_WqWk);
    cudaGetSymbolAddress((void**)&p_bv,   g_bv);
    cudaGetSymbolAddress((void**)&p_wihT, g_wihT);
    cudaGetSymbolAddress((void**)&p_whhT, g_whhT);
    cudaGetSymbolAddress((void**)&p_sA,   g_slotsA);
    cudaGetSymbolAddress((void**)&p_sB,   g_slotsB);
    cudaGetSymbolAddress((void**)&p_sn,   g_sn);
    cudaGetSymbolAddress((void**)&p_Qp,   g_Qp);
    cudaGetSymbolAddress((void**)&p_Uacc, g_Uacc);
    cudaGetSymbolAddress((void**)&p_inv,  g_inv);
    cudaGetSymbolAddress((void**)&p_cb,   g_cb);
    cudaGetSymbolAddress((void**)&p_upd,  g_upd);
    cudaGetSymbolAddress((void**)&p_gi,   g_gi);
    cudaGetSymbolAddress((void**)&p_gh,   g_gh);
    cudaGetSymbolAddress((void**)&p_h,    g_hbuf);

    // ---- prep ----
    prep_weights<<<768, 256>>>(Wk, Wv, ln_in_g, wih, whh);
    bias_vec<<<1, 512>>>(Wk, Wv, ln_in_b);
    sgemm_kernel<64,64,16,4,4,0><<<dim3(4, 4), 256>>>(
        Wq, p_WkgT, p_WqWk, 256, 256, 256, nullptr, nullptr, nullptr);
    wqbk_kernel<<<1, 256>>>(Wq);
    slots_init<<<512, 256>>>(noise, mu, lsig);
    ln_write<<<ROWS_IN/8, 256>>>(inputs);

    float* prev = p_sA;
    float* next = p_sB;
    for (int it = 0; it < 3; it++) {
        ln_rows<<<SROWS, 256>>>(prev, p_sn, ln_s_g, ln_s_b);
        sgemm_kernel<64,64,16,4,4,0><<<dim3(4, 8), 256>>>(
            p_sn, p_WqWk, p_Qp, SROWS, 256, 256, nullptr, nullptr, nullptr);
        qb_kernel<<<64, 256>>>();
        zero_iter<<<512, 256>>>();
        fused_attn<<<dim3(NTOK/512, BATCH), 256>>>();
        rowscale<<<2, 256>>>();
        sgemm_kernel<64,64,16,4,4,5><<<dim3(4, 8), 256>>>(
            p_Uacc, p_Wvg, p_upd, SROWS, 256, 256, p_bv, p_inv, p_cb);
        sgemm_kernel<64,64,16,4,4,1><<<dim3(12, 8), 256>>>(
            p_upd, p_wihT, p_gi, SROWS, 768, 256, b_ih, nullptr, nullptr);
        sgemm_kernel<64,64,16,4,4,1><<<dim3(12, 8), 256>>>(
            prev, p_whhT, p_gh, SROWS, 768, 256, b_hh, nullptr, nullptr);
        gate_kernel<<<512, 256>>>(prev, next);
        ln_rows<<<SROWS, 256>>>(next, p_sn, ln_m_g, ln_m_b);
        sgemm_kernel<64,64,16,4,4,2><<<dim3(16, 8), 256>>>(
            p_sn, mlp_w1, p_h, SROWS, 1024, 256, mlp_b1, nullptr, nullptr);
        sgemm_kernel<64,64,16,4,4,3><<<dim3(4, 8), 256>>>(
            p_h, mlp_w2, next, SROWS, 256, 1024, mlp_b2, nullptr, nullptr);
        float* tmp = prev; prev = next; next = tmp;
    }

    // ---- outputs: slots [B,S,D] then attn^T [B,S,N] ----
    copy_slots<<<SROWS*256/256, 256>>>(prev, out);
    transpose_attn<<<dim3(NTOK/256, BATCH), 256>>>(out + SROWS*256);
}

// round 7
// speedup vs baseline: 2.7524x; 1.3728x over previous
#include <cuda_runtime.h>
#include <math.h>

#define BATCH 64
#define NTOK  4096
#define ROWS_IN (BATCH*NTOK)   /* 262144 */
#define SROWS   (BATCH*8)      /* 512 */

// ---------------- device scratch ---------------------------------------------
__device__ float g_attn[2097152];        // [B][N][8]
__device__ float g_Uacc[SROWS*256];      // un-normalized attn^T @ xn
__device__ float g_colsum[SROWS];
__device__ float g_WkgT[65536];          // [d][c] = g[c]*Wk[c][d]
__device__ float g_Wvg[65536];           // [d][e] = g[d]*Wv[d][e]
__device__ float g_WqWk[65536];          // Wq @ WkgT      [f][d]
__device__ float g_W2[65536];            // gs[f]*WqWk[f][d]
__device__ float g_cs2[256];
__device__ float g_bb2[256];
__device__ float g_M1[256*768];          // Wvg @ wihT
__device__ float g_v1[768];              // bv @ wihT
__device__ float g_W3[256*1024];         // gm[f]*mlp_w1[f][j]
__device__ float g_cs3[1024];
__device__ float g_bb3[1024];
__device__ float g_bk[256];
__device__ float g_bv[256];
__device__ float g_wqbk[256];
__device__ float g_wqp[256];             // gs * wqbk
__device__ float g_c12[2];               // c1 = gs.wqbk, c2 = bs.wqbk
__device__ float g_wihT[256*768];
__device__ float g_whhT[256*768];
__device__ float g_slotsA[SROWS*256];
__device__ float g_slotsB[SROWS*256];
__device__ float g_Qp[SROWS*256];
__device__ float g_qb[SROWS];
__device__ float g_ms[SROWS];            // slot LN mean
__device__ float g_rs[SROWS];            // slot LN rstd
__device__ float g_m2[SROWS];            // post-gate LN mean
__device__ float g_r2[SROWS];            // post-gate LN rstd
__device__ float g_gi[SROWS*768];
__device__ float g_gh[SROWS*768];
__device__ float g_hbuf[SROWS*1024];

// ---------------- weight prep ------------------------------------------------
__global__ void prep1(const float* __restrict__ Wk, const float* __restrict__ Wv,
                      const float* __restrict__ g,
                      const float* __restrict__ wih, const float* __restrict__ whh) {
    int idx = blockIdx.x * 256 + threadIdx.x;   // up to 196608
    if (idx < 65536) {
        int d = idx >> 8, c = idx & 255;
        g_WkgT[idx] = g[c] * Wk[c*256 + d];
        g_Wvg[idx]  = g[idx >> 8] * Wv[idx];
    }
    if (idx < 196608) {
        int d = idx / 768, j = idx - d*768;
        g_wihT[idx] = wih[j*256 + d];
        g_whhT[idx] = whh[j*256 + d];
    }
}

// bk[d] = b.Wk[:,d], bv[e] = b.Wv[:,e]  — thread-per-output, coalesced loads
__global__ void bias_vec2(const float* __restrict__ Wk, const float* __restrict__ Wv,
                          const float* __restrict__ b) {
    int t = blockIdx.x * 128 + threadIdx.x;   // 0..511
    float s = 0.f;
    if (t < 256) {
        #pragma unroll 8
        for (int c = 0; c < 256; c++) s += b[c] * Wk[c*256 + t];
        g_bk[t] = s;
    } else {
        int d = t - 256;
        #pragma unroll 8
        for (int c = 0; c < 256; c++) s += b[c] * Wv[c*256 + d];
        g_bv[d] = s;
    }
}

// wqbk[e] = Wq[e,:] . bk — warp per row, coalesced
__global__ void wqbk2(const float* __restrict__ Wq) {
    int e    = blockIdx.x * 8 + (threadIdx.x >> 5);
    int lane = threadIdx.x & 31;
    const float4* w4 = (const float4*)(Wq + e*256);
    const float4* b4 = (const float4*)g_bk;
    float4 a = w4[lane], ba = b4[lane];
    float4 c = w4[lane+32], bc = b4[lane+32];
    float s = a.x*ba.x + a.y*ba.y + a.z*ba.z + a.w*ba.w
            + c.x*bc.x + c.y*bc.y + c.z*bc.z + c.w*bc.w;
    #pragma unroll
    for (int off = 16; off; off >>= 1) s += __shfl_xor_sync(0xffffffffu, s, off);
    if (lane == 0) g_wqbk[e] = s;
}

// wq' = gs*wqbk, c1 = gs.wqbk, c2 = bs.wqbk
__global__ void wqp_kernel(const float* __restrict__ gs, const float* __restrict__ bs) {
    int t = threadIdx.x;
    float w = g_wqbk[t];
    g_wqp[t] = gs[t] * w;
    float a = gs[t] * w, b = bs[t] * w;
    #pragma unroll
    for (int off = 16; off; off >>= 1) {
        a += __shfl_xor_sync(0xffffffffu, a, off);
        b += __shfl_xor_sync(0xffffffffu, b, off);
    }
    __shared__ float ra[8], rb[8];
    if ((t & 31) == 0) { ra[t >> 5] = a; rb[t >> 5] = b; }
    __syncthreads();
    if (t == 0) {
        float A = 0.f, B = 0.f;
        #pragma unroll
        for (int i = 0; i < 8; i++) { A += ra[i]; B += rb[i]; }
        g_c12[0] = A; g_c12[1] = B;
    }
}

// elementwise row-scales: W2' = gs∘WqWk ; W3' = gm∘mlp_w1
__global__ void fold_a(const float* __restrict__ gs, const float* __restrict__ gm,
                       const float* __restrict__ w1) {
    int idx = blockIdx.x * 256 + threadIdx.x;   // 262144
    if (idx < 65536) g_W2[idx] = gs[idx >> 8] * g_WqWk[idx];
    g_W3[idx] = gm[idx >> 10] * w1[idx];
}

// column sums / bias projections
__global__ void fold_b(const float* __restrict__ bs, const float* __restrict__ bm,
                       const float* __restrict__ w1, const float* __restrict__ b1) {
    int t = blockIdx.x * 256 + threadIdx.x;  // 0..2047
    if (t < 256) {
        float cs = 0.f, bb = 0.f;
        #pragma unroll 8
        for (int f = 0; f < 256; f++) {
            cs += g_W2[f*256 + t];
            bb += bs[f] * g_WqWk[f*256 + t];
        }
        g_cs2[t] = cs; g_bb2[t] = bb;
    } else if (t < 1280) {
        int j = t - 256;
        float cs = 0.f, bb = 0.f;
        #pragma unroll 8
        for (int f = 0; f < 256; f++) {
            cs += g_W3[f*1024 + j];
            bb += bm[f] * w1[f*1024 + j];
        }
        g_cs3[j] = cs; g_bb3[j] = bb + b1[j];
    } else {
        int j = t - 1280;  // < 768
        float s = 0.f;
        #pragma unroll 8
        for (int e = 0; e < 256; e++) s += g_bv[e] * g_wihT[e*768 + j];
        g_v1[j] = s;
    }
}

// ---------------- slots init -------------------------------------------------
__global__ void slots_init(const float* __restrict__ noise, const float* __restrict__ mu,
                           const float* __restrict__ lsig) {
    int idx = blockIdx.x * 256 + threadIdx.x;  // 131072
    int d = idx & 255;
    g_slotsA[idx] = mu[d] + expf(lsig[d]) * noise[idx];
}

// ---------------- per-iter stats: slot LN stats + qb + zero Uacc/colsum ------
__global__ void slot_stats(const float* __restrict__ slots) {
    int t = blockIdx.x * 256 + threadIdx.x;
    // zero duty: 64 blocks * 256 = 16384 threads -> 8 elems each
    #pragma unroll
    for (int i = 0; i < 8; i++) g_Uacc[t * 8 + i] = 0.f;
    if (t < SROWS) g_colsum[t] = 0.f;

    int row  = blockIdx.x * 8 + (threadIdx.x >> 5);
    int lane = threadIdx.x & 31;
    const float4* p = (const float4*)(slots + row*256);
    const float4* w4 = (const float4*)g_wqp;
    float4 a = p[lane], c = p[lane + 32];
    float4 wa = w4[lane], wc = w4[lane + 32];
    float s = a.x + a.y + a.z + a.w + c.x + c.y + c.z + c.w;
    float q = a.x*a.x + a.y*a.y + a.z*a.z + a.w*a.w
            + c.x*c.x + c.y*c.y + c.z*c.z + c.w*c.w;
    float d1 = a.x*wa.x + a.y*wa.y + a.z*wa.z + a.w*wa.w
             + c.x*wc.x + c.y*wc.y + c.z*wc.z + c.w*wc.w;
    #pragma unroll
    for (int off = 16; off; off >>= 1) {
        s  += __shfl_xor_sync(0xffffffffu, s, off);
        q  += __shfl_xor_sync(0xffffffffu, q, off);
        d1 += __shfl_xor_sync(0xffffffffu, d1, off);
    }
    if (lane == 0) {
        float m = s * (1.f/256.f);
        float var = q * (1.f/256.f) - m*m;
        float r = rsqrtf(var + 1e-5f);
        g_ms[row] = m;
        g_rs[row] = r;
        g_qb[row] = r * d1 - r * m * g_c12[0] + g_c12[1];
    }
}

// ---------------- generic tiled SGEMM ----------------------------------------
// MODE: 0 plain | 1 +bias | 3 bias+residual | 6 LN-fold (opt relu)
template<int BM, int BN, int BK, int TM, int TN, int MODE, bool RELU>
__global__ __launch_bounds__(256)
void sgemm_kernel(const float* __restrict__ A, const float* __restrict__ B,
                  float* __restrict__ C, int M, int N, int K,
                  const float* __restrict__ bias,
                  const float* __restrict__ rowm,
                  const float* __restrict__ rowr,
                  const float* __restrict__ colsumv) {
    static_assert((BM/TM)*(BN/TN) == 256, "256 threads");
    static_assert((BM*BK) == 4*256 && (BN*BK) == 4*256, "one float4 per thread per tile");
    __shared__ float As[BK][BM];
    __shared__ float Bs[BK][BN];
    int tid = threadIdx.x;
    int tx = tid % (BN/TN);
    int ty = tid / (BN/TN);
    int rowBase = blockIdx.y * BM;
    int colBase = blockIdx.x * BN;

    int a_r = tid / (BK/4);
    int a_c = (tid % (BK/4)) * 4;
    int b_r = tid / (BN/4);
    int b_c = (tid % (BN/4)) * 4;

    float acc[TM][TN];
    #pragma unroll
    for (int i = 0; i < TM; i++)
        #pragma unroll
        for (int j = 0; j < TN; j++) acc[i][j] = 0.f;

    for (int k0 = 0; k0 < K; k0 += BK) {
        float4 av = *(const float4*)&A[(size_t)(rowBase + a_r) * K + k0 + a_c];
        As[a_c + 0][a_r] = av.x;
        As[a_c + 1][a_r] = av.y;
        As[a_c + 2][a_r] = av.z;
        As[a_c + 3][a_r] = av.w;
        float4 bv = *(const float4*)&B[(size_t)(k0 + b_r) * N + colBase + b_c];
        *(float4*)&Bs[b_r][b_c] = bv;
        __syncthreads();
        #pragma unroll
        for (int kk = 0; kk < BK; kk++) {
            float af[TM], bf[TN];
            #pragma unroll
            for (int i = 0; i < TM; i++) af[i] = As[kk][ty*TM + i];
            #pragma unroll
            for (int j = 0; j < TN; j++) bf[j] = Bs[kk][tx*TN + j];
            #pragma unroll
            for (int i = 0; i < TM; i++)
                #pragma unroll
                for (int j = 0; j < TN; j++)
                    acc[i][j] += af[i] * bf[j];
        }
        __syncthreads();
    }

    #pragma unroll
    for (int i = 0; i < TM; i++) {
        int row = rowBase + ty*TM + i;
        float rm = 0.f, rr = 0.f;
        if constexpr (MODE == 6) { rm = rowm[row]; rr = rowr[row]; }
        #pragma unroll
        for (int j = 0; j < TN; j++) {
            int col = colBase + tx*TN + j;
            float v = acc[i][j];
            if constexpr (MODE == 1 || MODE == 3) v += bias[col];
            if constexpr (MODE == 3) v += C[(size_t)row * N + col];
            if constexpr (MODE == 6) {
                v = rr * v - rr * rm * colsumv[col] + bias[col];
                if constexpr (RELU) v = fmaxf(v, 0.f);
            }
            C[(size_t)row * N + col] = v;
        }
    }
}

// ---------------- merged gi/gh GEMM (grid.z: 0=gi from Uacc, 1=gh from prev) --
__global__ __launch_bounds__(256)
void gigh_kernel(const float* __restrict__ prev,
                 const float* __restrict__ b_ih, const float* __restrict__ b_hh) {
    constexpr int BM = 64, BN = 64, BK = 16, TM = 4, TN = 4;
    const int z = blockIdx.z;
    const float* A = z ? prev : g_Uacc;
    const float* B = z ? g_whhT : g_M1;
    float* C = z ? g_gh : g_gi;
    const int N = 768, K = 256;

    __shared__ float As[BK][BM];
    __shared__ float Bs[BK][BN];
    int tid = threadIdx.x;
    int tx = tid % (BN/TN);
    int ty = tid / (BN/TN);
    int rowBase = blockIdx.y * BM;
    int colBase = blockIdx.x * BN;
    int a_r = tid / (BK/4);
    int a_c = (tid % (BK/4)) * 4;
    int b_r = tid / (BN/4);
    int b_c = (tid % (BN/4)) * 4;

    float acc[TM][TN];
    #pragma unroll
    for (int i = 0; i < TM; i++)
        #pragma unroll
        for (int j = 0; j < TN; j++) acc[i][j] = 0.f;

    for (int k0 = 0; k0 < K; k0 += BK) {
        float4 av = *(const float4*)&A[(size_t)(rowBase + a_r) * K + k0 + a_c];
        As[a_c + 0][a_r] = av.x;
        As[a_c + 1][a_r] = av.y;
        As[a_c + 2][a_r] = av.z;
        As[a_c + 3][a_r] = av.w;
        float4 bv = *(const float4*)&B[(size_t)(k0 + b_r) * N + colBase + b_c];
        *(float4*)&Bs[b_r][b_c] = bv;
        __syncthreads();
        #pragma unroll
        for (int kk = 0; kk < BK; kk++) {
            float af[TM], bf[TN];
            #pragma unroll
            for (int i = 0; i < TM; i++) af[i] = As[kk][ty*TM + i];
            #pragma unroll
            for (int j = 0; j < TN; j++) bf[j] = Bs[kk][tx*TN + j];
            #pragma unroll
            for (int i = 0; i < TM; i++)
                #pragma unroll
                for (int j = 0; j < TN; j++)
                    acc[i][j] += af[i] * bf[j];
        }
        __syncthreads();
    }

    #pragma unroll
    for (int i = 0; i < TM; i++) {
        int row = rowBase + ty*TM + i;
        float inv = 0.f, cb = 0.f;
        if (z == 0) {
            float cs = g_colsum[row];
            inv = 1.f / (cs + 1e-8f);
            cb = cs * inv;
        }
        #pragma unroll
        for (int j = 0; j < TN; j++) {
            int col = colBase + tx*TN + j;
            float v = acc[i][j];
            if (z == 0) v = inv * v + cb * g_v1[col] + b_ih[col];
            else        v = v + b_hh[col];
            C[(size_t)row * N + col] = v;
        }
    }
}

// ---------------- fused logits+softmax+attn+U, inline input LN ---------------
__global__ __launch_bounds__(256) void fused_attn(const float* __restrict__ x) {
    int b = blockIdx.y;
    __shared__ float qs[2048];
    __shared__ float qb_s[8];
    __shared__ float cs[8];
    __shared__ float Ub[2048];
    int t = threadIdx.x;
    #pragma unroll
    for (int i = 0; i < 8; i++) {
        qs[i*256 + t] = g_Qp[b*2048 + i*256 + t];
        Ub[i*256 + t] = 0.f;
    }
    if (t < 8) { qb_s[t] = g_qb[b*8 + t]; cs[t] = 0.f; }
    __syncthreads();

    int warp = t >> 5, lane = t & 31;
    float regU[64];
    #pragma unroll
    for (int i = 0; i < 64; i++) regU[i] = 0.f;
    float lsum = 0.f;

    for (int it = 0; it < 64; it++) {
        int n = blockIdx.x * 512 + warp * 64 + it;
        const float* xr = x + (size_t)(b * NTOK + n) * 256;
        float4 x0 = *(const float4*)&xr[lane*4];
        float4 x1 = *(const float4*)&xr[128 + lane*4];
        // inline LN stats
        float s = x0.x + x0.y + x0.z + x0.w + x1.x + x1.y + x1.z + x1.w;
        float qq = x0.x*x0.x + x0.y*x0.y + x0.z*x0.z + x0.w*x0.w
                 + x1.x*x1.x + x1.y*x1.y + x1.z*x1.z + x1.w*x1.w;
        #pragma unroll
        for (int off = 16; off; off >>= 1) {
            s  += __shfl_xor_sync(0xffffffffu, s, off);
            qq += __shfl_xor_sync(0xffffffffu, qq, off);
        }
        float m = s * (1.f/256.f);
        float r = rsqrtf(qq * (1.f/256.f) - m*m + 1e-5f);
        x0.x = (x0.x-m)*r; x0.y = (x0.y-m)*r; x0.z = (x0.z-m)*r; x0.w = (x0.w-m)*r;
        x1.x = (x1.x-m)*r; x1.y = (x1.y-m)*r; x1.z = (x1.z-m)*r; x1.w = (x1.w-m)*r;

        float acc[8];
        #pragma unroll
        for (int sl = 0; sl < 8; sl++) {
            const float4 q0 = *(const float4*)&qs[sl*256 + lane*4];
            const float4 q1 = *(const float4*)&qs[sl*256 + 128 + lane*4];
            acc[sl] = x0.x*q0.x + x0.y*q0.y + x0.z*q0.z + x0.w*q0.w
                    + x1.x*q1.x + x1.y*q1.y + x1.z*q1.z + x1.w*q1.w;
        }
        #pragma unroll
        for (int sl = 0; sl < 8; sl++)
            #pragma unroll
            for (int off = 16; off; off >>= 1)
                acc[sl] += __shfl_xor_sync(0xffffffffu, acc[sl], off);
        float mx = -1e30f;
        #pragma unroll
        for (int sl = 0; sl < 8; sl++) {
            acc[sl] = (acc[sl] + qb_s[sl]) * 0.0625f;
            mx = fmaxf(mx, acc[sl]);
        }
        float a[8], se = 0.f;
        #pragma unroll
        for (int sl = 0; sl < 8; sl++) { a[sl] = expf(acc[sl] - mx); se += a[sl]; }
        float inv = 1.f / se;
        #pragma unroll
        for (int sl = 0; sl < 8; sl++) a[sl] *= inv;
        if (lane < 8) {
            float aval = 0.f;
            #pragma unroll
            for (int sl = 0; sl < 8; sl++) if (lane == sl) aval = a[sl];
            g_attn[(size_t)(b * NTOK + n) * 8 + lane] = aval;
            lsum += aval;
        }
        #pragma unroll
        for (int sl = 0; sl < 8; sl++) {
            regU[sl*8+0] += a[sl]*x0.x; regU[sl*8+1] += a[sl]*x0.y;
            regU[sl*8+2] += a[sl]*x0.z; regU[sl*8+3] += a[sl]*x0.w;
            regU[sl*8+4] += a[sl]*x1.x; regU[sl*8+5] += a[sl]*x1.y;
            regU[sl*8+6] += a[sl]*x1.z; regU[sl*8+7] += a[sl]*x1.w;
        }
    }
    #pragma unroll
    for (int sl = 0; sl < 8; sl++) {
        #pragma unroll
        for (int j = 0; j < 4; j++)
            atomicAdd(&Ub[sl*256 + 4*lane + j], regU[sl*8 + j]);
        #pragma unroll
        for (int j = 0; j < 4; j++)
            atomicAdd(&Ub[sl*256 + 128 + 4*lane + j], regU[sl*8 + 4 + j]);
    }
    if (lane < 8) atomicAdd(&cs[lane], lsum);
    __syncthreads();
    #pragma unroll
    for (int i = 0; i < 8; i++)
        atomicAdd(&g_Uacc[b*2048 + i*256 + t], Ub[i*256 + t]);
    if (t < 8) atomicAdd(&g_colsum[b*8 + t], cs[t]);
}

// ---------------- GRU gating + LN stats of result (block per row) ------------
__global__ void gate_stats(const float* __restrict__ prev, float* __restrict__ outp) {
    int row = blockIdx.x, d = threadIdx.x;
    const float* gi = g_gi + row*768;
    const float* gh = g_gh + row*768;
    float r = 1.f / (1.f + expf(-(gi[d]       + gh[d])));
    float z = 1.f / (1.f + expf(-(gi[256 + d] + gh[256 + d])));
    float n = tanhf(gi[512 + d] + r * gh[512 + d]);
    float v = (1.f - z) * n + z * prev[row*256 + d];
    outp[row*256 + d] = v;
    // block LN stats
    float s = v, q = v*v;
    #pragma unroll
    for (int off = 16; off; off >>= 1) {
        s += __shfl_xor_sync(0xffffffffu, s, off);
        q += __shfl_xor_sync(0xffffffffu, q, off);
    }
    __shared__ float red[16];
    int w = d >> 5, l = d & 31;
    if (l == 0) { red[w] = s; red[8 + w] = q; }
    __syncthreads();
    if (d == 0) {
        float S = 0.f, Q = 0.f;
        #pragma unroll
        for (int i = 0; i < 8; i++) { S += red[i]; Q += red[8 + i]; }
        float m = S * (1.f/256.f);
        float var = Q * (1.f/256.f) - m*m;
        g_m2[row] = m;
        g_r2[row] = rsqrtf(var + 1e-5f);
    }
}

// ---------------- final output: slots copy + attn transpose ------------------
__global__ void final_out(const float* __restrict__ slots, float* __restrict__ out) {
    int bid = blockIdx.x;
    int t = threadIdx.x;
    if (bid < 512) {
        out[bid*256 + t] = slots[bid*256 + t];
        return;
    }
    int idx = bid - 512;                  // 0..1023
    int b = idx >> 4;
    int base = (idx & 15) * 256;
    float* o = out + SROWS*256;
    __shared__ float sm[256*9];
    #pragma unroll
    for (int i = 0; i < 8; i++) {
        int lin = i*256 + t;
        float v = g_attn[(size_t)(b * NTOK + base) * 8 + lin];
        sm[(lin >> 3) * 9 + (lin & 7)] = v;
    }
    __syncthreads();
    #pragma unroll
    for (int s = 0; s < 8; s++)
        o[(size_t)b * 8 * NTOK + s * NTOK + base + t] = sm[t*9 + s];
}

// =============================================================================
extern "C" void kernel_launch(void* const* d_in, const int* in_sizes, int n_in,
                              void* d_out, int out_size) {
    const float* inputs   = (const float*)d_in[0];
    const float* noise    = (const float*)d_in[1];
    const float* mu       = (const float*)d_in[2];
    const float* lsig     = (const float*)d_in[3];
    const float* ln_in_g  = (const float*)d_in[4];
    const float* ln_in_b  = (const float*)d_in[5];
    const float* ln_s_g   = (const float*)d_in[6];
    const float* ln_s_b   = (const float*)d_in[7];
    const float* ln_m_g   = (const float*)d_in[8];
    const float* ln_m_b   = (const float*)d_in[9];
    const float* Wq       = (const float*)d_in[10];
    const float* Wk       = (const float*)d_in[11];
    const float* Wv       = (const float*)d_in[12];
    const float* wih      = (const float*)d_in[13];
    const float* whh      = (const float*)d_in[14];
    const float* b_ih     = (const float*)d_in[15];
    const float* b_hh     = (const float*)d_in[16];
    const float* mlp_w1   = (const float*)d_in[17];
    const float* mlp_b1   = (const float*)d_in[18];
    const float* mlp_w2   = (const float*)d_in[19];
    const float* mlp_b2   = (const float*)d_in[20];
    float* out = (float*)d_out;

    float *p_WkgT, *p_Wvg, *p_WqWk, *p_M1, *p_wihT;
    float *p_W2, *p_cs2, *p_bb2, *p_W3, *p_cs3, *p_bb3;
    float *p_sA, *p_sB, *p_Qp, *p_ms, *p_rs, *p_m2, *p_r2, *p_h;
    cudaGetSymbolAddress((void**)&p_WkgT, g_WkgT);
    cudaGetSymbolAddress((void**)&p_Wvg,  g_Wvg);
    cudaGetSymbolAddress((void**)&p_WqWk, g_WqWk);
    cudaGetSymbolAddress((void**)&p_M1,   g_M1);
    cudaGetSymbolAddress((void**)&p_wihT, g_wihT);
    cudaGetSymbolAddress((void**)&p_W2,   g_W2);
    cudaGetSymbolAddress((void**)&p_cs2,  g_cs2);
    cudaGetSymbolAddress((void**)&p_bb2,  g_bb2);
    cudaGetSymbolAddress((void**)&p_W3,   g_W3);
    cudaGetSymbolAddress((void**)&p_cs3,  g_cs3);
    cudaGetSymbolAddress((void**)&p_bb3,  g_bb3);
    cudaGetSymbolAddress((void**)&p_sA,   g_slotsA);
    cudaGetSymbolAddress((void**)&p_sB,   g_slotsB);
    cudaGetSymbolAddress((void**)&p_Qp,   g_Qp);
    cudaGetSymbolAddress((void**)&p_ms,   g_ms);
    cudaGetSymbolAddress((void**)&p_rs,   g_rs);
    cudaGetSymbolAddress((void**)&p_m2,   g_m2);
    cudaGetSymbolAddress((void**)&p_r2,   g_r2);
    cudaGetSymbolAddress((void**)&p_h,    g_hbuf);
    float *p_gi, *p_gh, *p_Uacc;
    cudaGetSymbolAddress((void**)&p_gi,   g_gi);
    cudaGetSymbolAddress((void**)&p_gh,   g_gh);
    cudaGetSymbolAddress((void**)&p_Uacc, g_Uacc);

    // ---- prep (one-time per call) ----
    prep1<<<768, 256>>>(Wk, Wv, ln_in_g, wih, whh);
    bias_vec2<<<4, 128>>>(Wk, Wv, ln_in_b);
    sgemm_kernel<64,64,16,4,4,0,false><<<dim3(4, 4), 256>>>(
        Wq, p_WkgT, p_WqWk, 256, 256, 256, nullptr, nullptr, nullptr, nullptr);
    wqbk2<<<32, 256>>>(Wq);
    wqp_kernel<<<1, 256>>>(ln_s_g, ln_s_b);
    sgemm_kernel<64,64,16,4,4,0,false><<<dim3(12, 4), 256>>>(
        p_Wvg, p_wihT, p_M1, 256, 768, 256, nullptr, nullptr, nullptr, nullptr);
    fold_a<<<1024, 256>>>(ln_s_g, ln_m_g, mlp_w1);
    fold_b<<<8, 256>>>(ln_s_b, ln_m_b, mlp_w1, mlp_b1);
    slots_init<<<512, 256>>>(noise, mu, lsig);

    float* prev = p_sA;
    float* next = p_sB;
    for (int it = 0; it < 3; it++) {
        slot_stats<<<64, 256>>>(prev);
        sgemm_kernel<64,64,16,4,4,6,false><<<dim3(4, 8), 256>>>(
            prev, p_W2, p_Qp, SROWS, 256, 256, p_bb2, p_ms, p_rs, p_cs2);
        fused_attn<<<dim3(NTOK/512, BATCH), 256>>>(inputs);
        gigh_kernel<<<dim3(12, 8, 2), 256>>>(prev, b_ih, b_hh);
        gate_stats<<<512, 256>>>(prev, next);
        sgemm_kernel<64,64,16,4,4,6,true><<<dim3(16, 8), 256>>>(
            next, p_W3, p_h, SROWS, 1024, 256, p_bb3, p_m2, p_r2, p_cs3);
        sgemm_kernel<64,64,16,4,4,3,false><<<dim3(4, 8), 256>>>(
            p_h, mlp_w2, next, SROWS, 256, 1024, mlp_b2, nullptr, nullptr, nullptr);
        float* tmp = prev; prev = next; next = tmp;
    }

    final_out<<<1536, 256>>>(prev, out);
}

// round 8
// speedup vs baseline: 2.8588x; 1.0387x over previous
#include <cuda_runtime.h>
#include <math.h>

#define BATCH 64
#define NTOK  4096
#define ROWS_IN (BATCH*NTOK)   /* 262144 */
#define SROWS   (BATCH*8)      /* 512 */

// ---------------- device scratch ---------------------------------------------
__device__ float g_attn[2097152];        // [B][N][8] (written final iter only)
__device__ float g_Uacc[SROWS*256];
__device__ float g_colsum[SROWS];
__device__ float g_WkgT[65536];          // [d][c] = g[c]*Wk[c][d]
__device__ float g_Wvg[65536];           // [d][e] = g[d]*Wv[d][e]
__device__ float g_WqWk[65536];          // Wq @ WkgT
__device__ float g_W2[65536];            // gs[f]*WqWk[f][d]
__device__ float g_cs2[256];
__device__ float g_bb2[256];
__device__ float g_M1[256*768];          // Wvg @ wihT
__device__ float g_v1[768];              // bv @ wihT
__device__ float g_W3[256*1024];         // gm[f]*mlp_w1[f][j]
__device__ float g_cs3[1024];
__device__ float g_bb3[1024];
__device__ float g_bk[256];
__device__ float g_bv[256];
__device__ float g_wqbk[256];
__device__ float g_wqp[256];
__device__ float g_c12[2];
__device__ float g_wihT[256*768];
__device__ float g_whhT[256*768];
__device__ float g_slotsA[SROWS*256];
__device__ float g_slotsB[SROWS*256];
__device__ float g_Qp[SROWS*256];
__device__ float g_qb[SROWS];
__device__ float g_gi[SROWS*768];
__device__ float g_gh[SROWS*768];
__device__ float g_hbuf[SROWS*1024];

// ============ PREP K1: weights prep + bias + slots init + zero ===============
__global__ void prep_init(const float* __restrict__ Wk, const float* __restrict__ Wv,
                          const float* __restrict__ g,
                          const float* __restrict__ wih, const float* __restrict__ whh,
                          const float* __restrict__ b,
                          const float* __restrict__ noise, const float* __restrict__ mu,
                          const float* __restrict__ lsig) {
    int idx = blockIdx.x * 256 + threadIdx.x;
    if (idx < 196608) {
        if (idx < 65536) {
            int d = idx >> 8, c = idx & 255;
            g_WkgT[idx] = g[c] * Wk[c*256 + d];
            g_Wvg[idx]  = g[idx >> 8] * Wv[idx];
        }
        int d = idx / 768, j = idx - d*768;
        g_wihT[idx] = wih[j*256 + d];
        g_whhT[idx] = whh[j*256 + d];
    } else if (idx < 197120) {
        int t = idx - 196608;
        float s = 0.f;
        if (t < 256) {
            #pragma unroll 8
            for (int c = 0; c < 256; c++) s += b[c] * Wk[c*256 + t];
            g_bk[t] = s;
        } else {
            int d = t - 256;
            #pragma unroll 8
            for (int c = 0; c < 256; c++) s += b[c] * Wv[c*256 + d];
            g_bv[d] = s;
        }
    } else if (idx < 328192) {
        int i = idx - 197120;
        int d = i & 255;
        g_slotsA[i] = mu[d] + expf(lsig[d]) * noise[i];
    } else if (idx < 459264) {
        int i = idx - 328192;
        g_Uacc[i] = 0.f;
        if (i < SROWS) g_colsum[i] = 0.f;
    }
}

// ============ PREP K2: WqWk gemm + M1 gemm + wqbk =============================
__global__ __launch_bounds__(256) void prep_gemm(const float* __restrict__ Wq) {
    int bx = blockIdx.x;
    int tid = threadIdx.x;
    if (bx >= 64) {
        // wqbk: warp-per-row dot with g_bk
        int e    = (bx - 64) * 8 + (tid >> 5);
        int lane = tid & 31;
        const float4* w4 = (const float4*)(Wq + e*256);
        const float4* b4 = (const float4*)g_bk;
        float4 a = w4[lane], ba = b4[lane];
        float4 c = w4[lane+32], bc = b4[lane+32];
        float s = a.x*ba.x + a.y*ba.y + a.z*ba.z + a.w*ba.w
                + c.x*bc.x + c.y*bc.y + c.z*bc.z + c.w*bc.w;
        #pragma unroll
        for (int off = 16; off; off >>= 1) s += __shfl_xor_sync(0xffffffffu, s, off);
        if (lane == 0) g_wqbk[e] = s;
        return;
    }
    const float* A; const float* B; float* C; int N, by, bcol;
    if (bx < 16) { A = Wq;    B = g_WkgT; C = g_WqWk; N = 256; by = bx >> 2;  bcol = bx & 3; }
    else { int u = bx - 16;    A = g_Wvg; B = g_wihT; C = g_M1;  N = 768; by = u / 12;  bcol = u % 12; }
    constexpr int BM=64, BN=64, BK=16, TM=4, TN=4;
    const int K = 256;
    __shared__ float As[BK][BM];
    __shared__ float Bs[BK][BN];
    int tx = tid % (BN/TN);
    int ty = tid / (BN/TN);
    int rowBase = by * BM;
    int colBase = bcol * BN;
    int a_r = tid / 4, a_c = (tid % 4) * 4;
    int b_r = tid / 16, b_c = (tid % 16) * 4;
    float acc[TM][TN];
    #pragma unroll
    for (int i = 0; i < TM; i++)
        #pragma unroll
        for (int j = 0; j < TN; j++) acc[i][j] = 0.f;
    for (int k0 = 0; k0 < K; k0 += BK) {
        float4 av = *(const float4*)&A[(size_t)(rowBase + a_r) * K + k0 + a_c];
        As[a_c+0][a_r] = av.x; As[a_c+1][a_r] = av.y;
        As[a_c+2][a_r] = av.z; As[a_c+3][a_r] = av.w;
        float4 bv = *(const float4*)&B[(size_t)(k0 + b_r) * N + colBase + b_c];
        *(float4*)&Bs[b_r][b_c] = bv;
        __syncthreads();
        #pragma unroll
        for (int kk = 0; kk < BK; kk++) {
            float af[TM], bf[TN];
            #pragma unroll
            for (int i = 0; i < TM; i++) af[i] = As[kk][ty*TM + i];
            #pragma unroll
            for (int j = 0; j < TN; j++) bf[j] = Bs[kk][tx*TN + j];
            #pragma unroll
            for (int i = 0; i < TM; i++)
                #pragma unroll
                for (int j = 0; j < TN; j++) acc[i][j] += af[i] * bf[j];
        }
        __syncthreads();
    }
    #pragma unroll
    for (int i = 0; i < TM; i++) {
        int row = rowBase + ty*TM + i;
        #pragma unroll
        for (int j = 0; j < TN; j++)
            C[(size_t)row * N + colBase + tx*TN + j] = acc[i][j];
    }
}

// ============ PREP K3: wqp/c12 + fold_a + fold_b ==============================
__global__ void prep_fold(const float* __restrict__ gs, const float* __restrict__ bs,
                          const float* __restrict__ gm, const float* __restrict__ bm,
                          const float* __restrict__ w1, const float* __restrict__ b1) {
    int bx = blockIdx.x, t = threadIdx.x;
    if (bx == 0) {
        float w = g_wqbk[t];
        g_wqp[t] = gs[t] * w;
        float a = gs[t] * w, b = bs[t] * w;
        #pragma unroll
        for (int off = 16; off; off >>= 1) {
            a += __shfl_xor_sync(0xffffffffu, a, off);
            b += __shfl_xor_sync(0xffffffffu, b, off);
        }
        __shared__ float ra[8], rb[8];
        if ((t & 31) == 0) { ra[t >> 5] = a; rb[t >> 5] = b; }
        __syncthreads();
        if (t == 0) {
            float A = 0.f, B = 0.f;
            #pragma unroll
            for (int i = 0; i < 8; i++) { A += ra[i]; B += rb[i]; }
            g_c12[0] = A; g_c12[1] = B;
        }
    } else if (bx <= 1024) {
        int idx = (bx - 1) * 256 + t;   // < 262144
        if (idx < 65536) g_W2[idx] = gs[idx >> 8] * g_WqWk[idx];
        g_W3[idx] = gm[idx >> 10] * w1[idx];
    } else {
        int u = (bx - 1025) * 256 + t;  // < 2048
        if (u < 256) {
            float cs = 0.f, bb = 0.f;
            #pragma unroll 8
            for (int f = 0; f < 256; f++) {
                float w = g_WqWk[f*256 + u];
                cs += gs[f] * w;
                bb += bs[f] * w;
            }
            g_cs2[u] = cs; g_bb2[u] = bb;
        } else if (u < 1280) {
            int j = u - 256;
            float cs = 0.f, bb = 0.f;
            #pragma unroll 8
            for (int f = 0; f < 256; f++) {
                cs += gm[f] * w1[f*1024 + j];
                bb += bm[f] * w1[f*1024 + j];
            }
            g_cs3[j] = cs; g_bb3[j] = bb + b1[j];
        } else {
            int j = u - 1280;  // < 768
            float s = 0.f;
            #pragma unroll 8
            for (int e = 0; e < 256; e++) s += g_bv[e] * g_wihT[e*768 + j];
            g_v1[j] = s;
        }
    }
}

// ============ Qp GEMM with in-block slot-LN stats + qb ========================
__global__ __launch_bounds__(256) void qp_gemm(const float* __restrict__ A) {
    constexpr int BM=64, BN=64, BK=16, TM=4, TN=4;
    const int N = 256, K = 256;
    __shared__ float As[BK][BM];
    __shared__ float Bs[BK][BN];
    __shared__ float sm_m[64], sm_r[64];
    int tid = threadIdx.x;
    int w = tid >> 5, lane = tid & 31;
    int rowBase = blockIdx.y * BM;
    int colBase = blockIdx.x * BN;
    float c1 = g_c12[0], c2v = g_c12[1];
    #pragma unroll
    for (int rr = 0; rr < 8; rr++) {
        int row = rowBase + w*8 + rr;
        const float4* p  = (const float4*)(A + row*256);
        const float4* w4 = (const float4*)g_wqp;
        float4 a = p[lane], c = p[lane+32];
        float4 wa = w4[lane], wc = w4[lane+32];
        float s = a.x+a.y+a.z+a.w + c.x+c.y+c.z+c.w;
        float q = a.x*a.x+a.y*a.y+a.z*a.z+a.w*a.w
                + c.x*c.x+c.y*c.y+c.z*c.z+c.w*c.w;
        float d1 = a.x*wa.x+a.y*wa.y+a.z*wa.z+a.w*wa.w
                 + c.x*wc.x+c.y*wc.y+c.z*wc.z+c.w*wc.w;
        #pragma unroll
        for (int off = 16; off; off >>= 1) {
            s  += __shfl_xor_sync(0xffffffffu, s, off);
            q  += __shfl_xor_sync(0xffffffffu, q, off);
            d1 += __shfl_xor_sync(0xffffffffu, d1, off);
        }
        if (lane == 0) {
            float m = s * (1.f/256.f);
            float r = rsqrtf(q * (1.f/256.f) - m*m + 1e-5f);
            sm_m[w*8+rr] = m; sm_r[w*8+rr] = r;
            if (blockIdx.x == 0) g_qb[row] = r*d1 - r*m*c1 + c2v;
        }
    }
    __syncthreads();
    int tx = tid % (BN/TN);
    int ty = tid / (BN/TN);
    int a_r = tid / 4, a_c = (tid % 4) * 4;
    int b_r = tid / 16, b_c = (tid % 16) * 4;
    float acc[TM][TN];
    #pragma unroll
    for (int i = 0; i < TM; i++)
        #pragma unroll
        for (int j = 0; j < TN; j++) acc[i][j] = 0.f;
    for (int k0 = 0; k0 < K; k0 += BK) {
        float4 av = *(const float4*)&A[(size_t)(rowBase + a_r) * K + k0 + a_c];
        As[a_c+0][a_r] = av.x; As[a_c+1][a_r] = av.y;
        As[a_c+2][a_r] = av.z; As[a_c+3][a_r] = av.w;
        float4 bv = *(const float4*)&g_W2[(size_t)(k0 + b_r) * N + colBase + b_c];
        *(float4*)&Bs[b_r][b_c] = bv;
        __syncthreads();
        #pragma unroll
        for (int kk = 0; kk < BK; kk++) {
            float af[TM], bf[TN];
            #pragma unroll
            for (int i = 0; i < TM; i++) af[i] = As[kk][ty*TM + i];
            #pragma unroll
            for (int j = 0; j < TN; j++) bf[j] = Bs[kk][tx*TN + j];
            #pragma unroll
            for (int i = 0; i < TM; i++)
                #pragma unroll
                for (int j = 0; j < TN; j++) acc[i][j] += af[i] * bf[j];
        }
        __syncthreads();
    }
    #pragma unroll
    for (int i = 0; i < TM; i++) {
        int local = ty*TM + i;
        int row = rowBase + local;
        float rm = sm_m[local], rr_ = sm_r[local];
        #pragma unroll
        for (int j = 0; j < TN; j++) {
            int col = colBase + tx*TN + j;
            g_Qp[(size_t)row * N + col] = rr_*(acc[i][j] - rm*g_cs2[col]) + g_bb2[col];
        }
    }
}

// ============ fused logits+softmax+attn+U, inline input LN ====================
__global__ __launch_bounds__(256) void fused_attn(const float* __restrict__ x,
                                                  int store_attn) {
    int b = blockIdx.y;
    __shared__ float qs[2048];
    __shared__ float qb_s[8];
    __shared__ float cs[8];
    __shared__ float Ub[2048];
    int t = threadIdx.x;
    #pragma unroll
    for (int i = 0; i < 8; i++) {
        qs[i*256 + t] = g_Qp[b*2048 + i*256 + t];
        Ub[i*256 + t] = 0.f;
    }
    if (t < 8) { qb_s[t] = g_qb[b*8 + t]; cs[t] = 0.f; }
    __syncthreads();

    int warp = t >> 5, lane = t & 31;
    float regU[64];
    #pragma unroll
    for (int i = 0; i < 64; i++) regU[i] = 0.f;
    float lsum = 0.f;

    for (int it = 0; it < 64; it++) {
        int n = blockIdx.x * 512 + warp * 64 + it;
        const float* xr = x + (size_t)(b * NTOK + n) * 256;
        float4 x0 = *(const float4*)&xr[lane*4];
        float4 x1 = *(const float4*)&xr[128 + lane*4];
        float s = x0.x + x0.y + x0.z + x0.w + x1.x + x1.y + x1.z + x1.w;
        float qq = x0.x*x0.x + x0.y*x0.y + x0.z*x0.z + x0.w*x0.w
                 + x1.x*x1.x + x1.y*x1.y + x1.z*x1.z + x1.w*x1.w;
        #pragma unroll
        for (int off = 16; off; off >>= 1) {
            s  += __shfl_xor_sync(0xffffffffu, s, off);
            qq += __shfl_xor_sync(0xffffffffu, qq, off);
        }
        float m = s * (1.f/256.f);
        float r = rsqrtf(qq * (1.f/256.f) - m*m + 1e-5f);
        x0.x = (x0.x-m)*r; x0.y = (x0.y-m)*r; x0.z = (x0.z-m)*r; x0.w = (x0.w-m)*r;
        x1.x = (x1.x-m)*r; x1.y = (x1.y-m)*r; x1.z = (x1.z-m)*r; x1.w = (x1.w-m)*r;

        float acc[8];
        #pragma unroll
        for (int sl = 0; sl < 8; sl++) {
            const float4 q0 = *(const float4*)&qs[sl*256 + lane*4];
            const float4 q1 = *(const float4*)&qs[sl*256 + 128 + lane*4];
            acc[sl] = x0.x*q0.x + x0.y*q0.y + x0.z*q0.z + x0.w*q0.w
                    + x1.x*q1.x + x1.y*q1.y + x1.z*q1.z + x1.w*q1.w;
        }
        #pragma unroll
        for (int sl = 0; sl < 8; sl++)
            #pragma unroll
            for (int off = 16; off; off >>= 1)
                acc[sl] += __shfl_xor_sync(0xffffffffu, acc[sl], off);
        float mx = -1e30f;
        #pragma unroll
        for (int sl = 0; sl < 8; sl++) {
            acc[sl] = (acc[sl] + qb_s[sl]) * 0.0625f;
            mx = fmaxf(mx, acc[sl]);
        }
        float a[8], se = 0.f;
        #pragma unroll
        for (int sl = 0; sl < 8; sl++) { a[sl] = expf(acc[sl] - mx); se += a[sl]; }
        float inv = 1.f / se;
        #pragma unroll
        for (int sl = 0; sl < 8; sl++) a[sl] *= inv;
        if (lane < 8) {
            float aval = 0.f;
            #pragma unroll
            for (int sl = 0; sl < 8; sl++) if (lane == sl) aval = a[sl];
            lsum += aval;
            if (store_attn) g_attn[(size_t)(b * NTOK + n) * 8 + lane] = aval;
        }
        #pragma unroll
        for (int sl = 0; sl < 8; sl++) {
            regU[sl*8+0] += a[sl]*x0.x; regU[sl*8+1] += a[sl]*x0.y;
            regU[sl*8+2] += a[sl]*x0.z; regU[sl*8+3] += a[sl]*x0.w;
            regU[sl*8+4] += a[sl]*x1.x; regU[sl*8+5] += a[sl]*x1.y;
            regU[sl*8+6] += a[sl]*x1.z; regU[sl*8+7] += a[sl]*x1.w;
        }
    }
    #pragma unroll
    for (int sl = 0; sl < 8; sl++) {
        #pragma unroll
        for (int j = 0; j < 4; j++)
            atomicAdd(&Ub[sl*256 + 4*lane + j], regU[sl*8 + j]);
        #pragma unroll
        for (int j = 0; j < 4; j++)
            atomicAdd(&Ub[sl*256 + 128 + 4*lane + j], regU[sl*8 + 4 + j]);
    }
    if (lane < 8) atomicAdd(&cs[lane], lsum);
    __syncthreads();
    #pragma unroll
    for (int i = 0; i < 8; i++)
        atomicAdd(&g_Uacc[b*2048 + i*256 + t], Ub[i*256 + t]);
    if (t < 8) atomicAdd(&g_colsum[b*8 + t], cs[t]);
}

// ============ merged gi/gh GEMM ===============================================
__global__ __launch_bounds__(256)
void gigh_kernel(const float* __restrict__ prev,
                 const float* __restrict__ b_ih, const float* __restrict__ b_hh) {
    constexpr int BM = 64, BN = 64, BK = 16, TM = 4, TN = 4;
    const int z = blockIdx.z;
    const float* A = z ? prev : g_Uacc;
    const float* B = z ? g_whhT : g_M1;
    float* C = z ? g_gh : g_gi;
    const int N = 768, K = 256;

    __shared__ float As[BK][BM];
    __shared__ float Bs[BK][BN];
    int tid = threadIdx.x;
    int tx = tid % (BN/TN);
    int ty = tid / (BN/TN);
    int rowBase = blockIdx.y * BM;
    int colBase = blockIdx.x * BN;
    int a_r = tid / 4, a_c = (tid % 4) * 4;
    int b_r = tid / 16, b_c = (tid % 16) * 4;

    float acc[TM][TN];
    #pragma unroll
    for (int i = 0; i < TM; i++)
        #pragma unroll
        for (int j = 0; j < TN; j++) acc[i][j] = 0.f;

    for (int k0 = 0; k0 < K; k0 += BK) {
        float4 av = *(const float4*)&A[(size_t)(rowBase + a_r) * K + k0 + a_c];
        As[a_c+0][a_r] = av.x; As[a_c+1][a_r] = av.y;
        As[a_c+2][a_r] = av.z; As[a_c+3][a_r] = av.w;
        float4 bv = *(const float4*)&B[(size_t)(k0 + b_r) * N + colBase + b_c];
        *(float4*)&Bs[b_r][b_c] = bv;
        __syncthreads();
        #pragma unroll
        for (int kk = 0; kk < BK; kk++) {
            float af[TM], bf[TN];
            #pragma unroll
            for (int i = 0; i < TM; i++) af[i] = As[kk][ty*TM + i];
            #pragma unroll
            for (int j = 0; j < TN; j++) bf[j] = Bs[kk][tx*TN + j];
            #pragma unroll
            for (int i = 0; i < TM; i++)
                #pragma unroll
                for (int j = 0; j < TN; j++) acc[i][j] += af[i] * bf[j];
        }
        __syncthreads();
    }

    #pragma unroll
    for (int i = 0; i < TM; i++) {
        int row = rowBase + ty*TM + i;
        float inv = 0.f, cb = 0.f;
        if (z == 0) {
            float csv = g_colsum[row];
            inv = 1.f / (csv + 1e-8f);
            cb = csv * inv;
        }
        #pragma unroll
        for (int j = 0; j < TN; j++) {
            int col = colBase + tx*TN + j;
            float v = acc[i][j];
            if (z == 0) v = inv * v + cb * g_v1[col] + b_ih[col];
            else        v = v + b_hh[col];
            C[(size_t)row * N + col] = v;
        }
    }
}

// ============ GRU gating + zero next-iter accumulators ========================
__global__ void gate_zero(const float* __restrict__ prev, float* __restrict__ outp) {
    int row = blockIdx.x, d = threadIdx.x;
    const float* gi = g_gi + row*768;
    const float* gh = g_gh + row*768;
    float r = 1.f / (1.f + expf(-(gi[d]       + gh[d])));
    float z = 1.f / (1.f + expf(-(gi[256 + d] + gh[256 + d])));
    float n = tanhf(gi[512 + d] + r * gh[512 + d]);
    outp[row*256 + d] = (1.f - z) * n + z * prev[row*256 + d];
    g_Uacc[row*256 + d] = 0.f;
    if (d == 0) g_colsum[row] = 0.f;
}

// ============ MLP1 GEMM with in-block LN stats + relu =========================
__global__ __launch_bounds__(256) void mlp1_kernel(const float* __restrict__ A) {
    constexpr int BM=64, BN=64, BK=16, TM=4, TN=4;
    const int N = 1024, K = 256;
    __shared__ float As[BK][BM];
    __shared__ float Bs[BK][BN];
    __shared__ float sm_m[64], sm_r[64];
    int tid = threadIdx.x;
    int w = tid >> 5, lane = tid & 31;
    int rowBase = blockIdx.y * BM;
    int colBase = blockIdx.x * BN;
    #pragma unroll
    for (int rr = 0; rr < 8; rr++) {
        int row = rowBase + w*8 + rr;
        const float4* p = (const float4*)(A + row*256);
        float4 a = p[lane], c = p[lane+32];
        float s = a.x+a.y+a.z+a.w + c.x+c.y+c.z+c.w;
        float q = a.x*a.x+a.y*a.y+a.z*a.z+a.w*a.w
                + c.x*c.x+c.y*c.y+c.z*c.z+c.w*c.w;
        #pragma unroll
        for (int off = 16; off; off >>= 1) {
            s += __shfl_xor_sync(0xffffffffu, s, off);
            q += __shfl_xor_sync(0xffffffffu, q, off);
        }
        if (lane == 0) {
            float m = s * (1.f/256.f);
            sm_m[w*8+rr] = m;
            sm_r[w*8+rr] = rsqrtf(q * (1.f/256.f) - m*m + 1e-5f);
        }
    }
    __syncthreads();
    int tx = tid % (BN/TN);
    int ty = tid / (BN/TN);
    int a_r = tid / 4, a_c = (tid % 4) * 4;
    int b_r = tid / 16, b_c = (tid % 16) * 4;
    float acc[TM][TN];
    #pragma unroll
    for (int i = 0; i < TM; i++)
        #pragma unroll
        for (int j = 0; j < TN; j++) acc[i][j] = 0.f;
    for (int k0 = 0; k0 < K; k0 += BK) {
        float4 av = *(const float4*)&A[(size_t)(rowBase + a_r) * K + k0 + a_c];
        As[a_c+0][a_r] = av.x; As[a_c+1][a_r] = av.y;
        As[a_c+2][a_r] = av.z; As[a_c+3][a_r] = av.w;
        float4 bv = *(const float4*)&g_W3[(size_t)(k0 + b_r) * N + colBase + b_c];
        *(float4*)&Bs[b_r][b_c] = bv;
        __syncthreads();
        #pragma unroll
        for (int kk = 0; kk < BK; kk++) {
            float af[TM], bf[TN];
            #pragma unroll
            for (int i = 0; i < TM; i++) af[i] = As[kk][ty*TM + i];
            #pragma unroll
            for (int j = 0; j < TN; j++) bf[j] = Bs[kk][tx*TN + j];
            #pragma unroll
            for (int i = 0; i < TM; i++)
                #pragma unroll
                for (int j = 0; j < TN; j++) acc[i][j] += af[i] * bf[j];
        }
        __syncthreads();
    }
    #pragma unroll
    for (int i = 0; i < TM; i++) {
        int local = ty*TM + i;
        int row = rowBase + local;
        float rm = sm_m[local], rr_ = sm_r[local];
        #pragma unroll
        for (int j = 0; j < TN; j++) {
            int col = colBase + tx*TN + j;
            float v = rr_*(acc[i][j] - rm*g_cs3[col]) + g_bb3[col];
            g_hbuf[(size_t)row * N + col] = fmaxf(v, 0.f);
        }
    }
}

// ============ MLP2 GEMM: h @ w2 + b2 + residual -> dst ========================
__global__ __launch_bounds__(256) void mlp2_kernel(const float* __restrict__ resid,
                                                   float* __restrict__ dst,
                                                   const float* __restrict__ Bw,
                                                   const float* __restrict__ b2) {
    constexpr int BM=64, BN=64, BK=16, TM=4, TN=4;
    const int N = 256, K = 1024;
    const float* A = g_hbuf;
    __shared__ float As[BK][BM];
    __shared__ float Bs[BK][BN];
    int tid = threadIdx.x;
    int tx = tid % (BN/TN);
    int ty = tid / (BN/TN);
    int rowBase = blockIdx.y * BM;
    int colBase = blockIdx.x * BN;
    int a_r = tid / 4, a_c = (tid % 4) * 4;
    int b_r = tid / 16, b_c = (tid % 16) * 4;
    float acc[TM][TN];
    #pragma unroll
    for (int i = 0; i < TM; i++)
        #pragma unroll
        for (int j = 0; j < TN; j++) acc[i][j] = 0.f;
    for (int k0 = 0; k0 < K; k0 += BK) {
        float4 av = *(const float4*)&A[(size_t)(rowBase + a_r) * K + k0 + a_c];
        As[a_c+0][a_r] = av.x; As[a_c+1][a_r] = av.y;
        As[a_c+2][a_r] = av.z; As[a_c+3][a_r] = av.w;
        float4 bv = *(const float4*)&Bw[(size_t)(k0 + b_r) * N + colBase + b_c];
        *(float4*)&Bs[b_r][b_c] = bv;
        __syncthreads();
        #pragma unroll
        for (int kk = 0; kk < BK; kk++) {
            float af[TM], bf[TN];
            #pragma unroll
            for (int i = 0; i < TM; i++) af[i] = As[kk][ty*TM + i];
            #pragma unroll
            for (int j = 0; j < TN; j++) bf[j] = Bs[kk][tx*TN + j];
            #pragma unroll
            for (int i = 0; i < TM; i++)
                #pragma unroll
                for (int j = 0; j < TN; j++) acc[i][j] += af[i] * bf[j];
        }
        __syncthreads();
    }
    #pragma unroll
    for (int i = 0; i < TM; i++) {
        int row = rowBase + ty*TM + i;
        #pragma unroll
        for (int j = 0; j < TN; j++) {
            int col = colBase + tx*TN + j;
            dst[(size_t)row * N + col] =
                acc[i][j] + b2[col] + resid[(size_t)row * N + col];
        }
    }
}

// ============ attn transpose [B,N,8] -> [B,8,N] ===============================
__global__ void attn_out(float* __restrict__ o) {
    int idx = blockIdx.x;                 // 0..1023
    int b = idx >> 4;
    int base = (idx & 15) * 256;
    int t = threadIdx.x;
    __shared__ float sm[256*9];
    #pragma unroll
    for (int i = 0; i < 8; i++) {
        int lin = i*256 + t;
        float v = g_attn[(size_t)(b * NTOK + base) * 8 + lin];
        sm[(lin >> 3) * 9 + (lin & 7)] = v;
    }
    __syncthreads();
    #pragma unroll
    for (int s = 0; s < 8; s++)
        o[(size_t)b * 8 * NTOK + s * NTOK + base + t] = sm[t*9 + s];
}

// =============================================================================
extern "C" void kernel_launch(void* const* d_in, const int* in_sizes, int n_in,
                              void* d_out, int out_size) {
    const float* inputs   = (const float*)d_in[0];
    const float* noise    = (const float*)d_in[1];
    const float* mu       = (const float*)d_in[2];
    const float* lsig     = (const float*)d_in[3];
    const float* ln_in_g  = (const float*)d_in[4];
    const float* ln_in_b  = (const float*)d_in[5];
    const float* ln_s_g   = (const float*)d_in[6];
    const float* ln_s_b   = (const float*)d_in[7];
    const float* ln_m_g   = (const float*)d_in[8];
    const float* ln_m_b   = (const float*)d_in[9];
    const float* Wq       = (const float*)d_in[10];
    const float* Wk       = (const float*)d_in[11];
    const float* Wv       = (const float*)d_in[12];
    const float* b_ih     = (const float*)d_in[15];
    const float* b_hh     = (const float*)d_in[16];
    const float* mlp_w1   = (const float*)d_in[17];
    const float* mlp_b1   = (const float*)d_in[18];
    const float* mlp_w2   = (const float*)d_in[19];
    const float* mlp_b2   = (const float*)d_in[20];
    const float* wih      = (const float*)d_in[13];
    const float* whh      = (const float*)d_in[14];
    float* out = (float*)d_out;

    float *p_sA, *p_sB;
    cudaGetSymbolAddress((void**)&p_sA, g_slotsA);
    cudaGetSymbolAddress((void**)&p_sB, g_slotsB);

    prep_init<<<1794, 256>>>(Wk, Wv, ln_in_g, wih, whh, ln_in_b, noise, mu, lsig);
    prep_gemm<<<96, 256>>>(Wq);
    prep_fold<<<1033, 256>>>(ln_s_g, ln_s_b, ln_m_g, ln_m_b, mlp_w1, mlp_b1);

    float* prev = p_sA;
    float* next = p_sB;
    for (int it = 0; it < 3; it++) {
        qp_gemm<<<dim3(4, 8), 256>>>(prev);
        fused_attn<<<dim3(NTOK/512, BATCH), 256>>>(inputs, it == 2 ? 1 : 0);
        gigh_kernel<<<dim3(12, 8, 2), 256>>>(prev, b_ih, b_hh);
        gate_zero<<<512, 256>>>(prev, next);
        mlp1_kernel<<<dim3(16, 8), 256>>>(next);
        mlp2_kernel<<<dim3(4, 8), 256>>>(next, it == 2 ? out : next, mlp_w2, mlp_b2);
        float* tmp = prev; prev = next; next = tmp;
    }

    attn_out<<<1024, 256>>>(out + SROWS*256);
}